// round 6
// baseline (speedup 1.0000x reference)
#include <cuda_runtime.h>
#include <math_constants.h>

#define NPTS   16384
#define KNN    10
#define NL     11                 // K+1 slots per chunk list (self may occupy one)
#define NCHUNK 2
#define CHUNK  (NPTS / NCHUNK)    // 8192
#define QPB    128                // threads per block in knn kernel
#define QPT    2                  // queries per thread
#define QPC    (QPB * QPT)        // queries per CTA = 256
#define UNR    4                  // candidates per prefetch group

// (-2x, -2y, -2z, x^2+y^2+z^2) per point
__device__ float4 g_pos4[NPTS];
// accumulators: 0 sparsity Σ|op|, 1 opacity Σ(op-.5)^2, 2 scale Σ|s-1|, 3 smooth Σ|Δop|
__device__ float g_acc[4];
// per-chunk candidate lists
__device__ float g_nd[NCHUNK][NPTS][NL];
__device__ int   g_ni[NCHUNK][NPTS][NL];

__device__ __forceinline__ float warp_sum(float v) {
#pragma unroll
    for (int o = 16; o; o >>= 1) v += __shfl_xor_sync(0xffffffffu, v, o);
    return v;
}

__global__ void init_kernel() {
    if (threadIdx.x < 4) g_acc[threadIdx.x] = 0.0f;
}

// precompute pos4 + the three cheap losses
__global__ void prep_kernel(const float* __restrict__ pos,
                            const float* __restrict__ op,
                            const float* __restrict__ sc) {
    int i = blockIdx.x * blockDim.x + threadIdx.x;   // grid covers exactly NPTS
    float x = pos[3 * i + 0], y = pos[3 * i + 1], z = pos[3 * i + 2];
    float sq = fmaf(z, z, fmaf(y, y, x * x));
    g_pos4[i] = make_float4(-2.0f * x, -2.0f * y, -2.0f * z, sq);

    float o  = op[i];
    float sp = fabsf(o);
    float ol = (o - 0.5f) * (o - 0.5f);
    float sl = fabsf(sc[3 * i + 0] - 1.0f)
             + fabsf(sc[3 * i + 1] - 1.0f)
             + fabsf(sc[3 * i + 2] - 1.0f);
    sp = warp_sum(sp);
    ol = warp_sum(ol);
    sl = warp_sum(sl);
    if ((threadIdx.x & 31) == 0) {
        atomicAdd(&g_acc[0], sp);
        atomicAdd(&g_acc[1], ol);
        atomicAdd(&g_acc[2], sl);
    }
}

#define INSERT(bd, bi, dval, ival)                                        \
    do {                                                                  \
        if ((dval) < bd[NL - 1]) {                                        \
            bd[NL - 1] = (dval);                                          \
            bi[NL - 1] = (ival);                                          \
            _Pragma("unroll")                                             \
            for (int k = NL - 1; k > 0; --k) {                            \
                if (bd[k] < bd[k - 1]) {                                  \
                    float td = bd[k]; bd[k] = bd[k - 1]; bd[k - 1] = td;  \
                    int   ti = bi[k]; bi[k] = bi[k - 1]; bi[k - 1] = ti;  \
                }                                                         \
            }                                                             \
        }                                                                 \
    } while (0)

// 2-queries-per-thread KNN over one 8192-candidate chunk.
// grid = (NPTS/QPC) * NCHUNK = 128 blocks of 128 threads.
// Full chunk staged in 128KB dynamic smem; UNR-wide prefetched candidate groups.
__global__ void __launch_bounds__(QPB) knn_kernel(const float* __restrict__ pos) {
    extern __shared__ float4 tile[];   // CHUNK float4 = 128KB

    const int chunk = blockIdx.x & (NCHUNK - 1);
    const int qA    = (blockIdx.x >> 1) * QPC + threadIdx.x;
    const int qB    = qA + QPB;

    const float axx = pos[3 * qA + 0], axy = pos[3 * qA + 1], axz = pos[3 * qA + 2];
    const float bxx = pos[3 * qB + 0], bxy = pos[3 * qB + 1], bxz = pos[3 * qB + 2];
    const float asq = fmaf(axz, axz, fmaf(axy, axy, axx * axx));
    const float bsq = fmaf(bxz, bxz, fmaf(bxy, bxy, bxx * bxx));

    float bdA[NL], bdB[NL];
    int   biA[NL], biB[NL];
#pragma unroll
    for (int k = 0; k < NL; k++) {
        bdA[k] = CUDART_INF_F; biA[k] = -1;
        bdB[k] = CUDART_INF_F; biB[k] = -1;
    }

    const int base = chunk * CHUNK;
#pragma unroll
    for (int r = 0; r < CHUNK / QPB; r++)
        tile[r * QPB + threadIdx.x] = g_pos4[base + r * QPB + threadIdx.x];
    __syncthreads();

    // prefetch first group
    float4 p[UNR];
#pragma unroll
    for (int u = 0; u < UNR; u++) p[u] = tile[u];

#pragma unroll 2
    for (int c = 0; c < CHUNK; c += UNR) {
        // prefetch next group (wraps harmlessly on the last iteration)
        float4 n[UNR];
#pragma unroll
        for (int u = 0; u < UNR; u++)
            n[u] = tile[(c + UNR + u) & (CHUNK - 1)];

        // distances for both queries — 8 independent FMA trees
        float dA[UNR], dB[UNR];
#pragma unroll
        for (int u = 0; u < UNR; u++) {
            dA[u] = asq + fmaf(p[u].x, axx, fmaf(p[u].y, axy, fmaf(p[u].z, axz, p[u].w)));
            dB[u] = bsq + fmaf(p[u].x, bxx, fmaf(p[u].y, bxy, fmaf(p[u].z, bxz, p[u].w)));
        }

#pragma unroll
        for (int u = 0; u < UNR; u++) INSERT(bdA, biA, dA[u], base + c + u);
#pragma unroll
        for (int u = 0; u < UNR; u++) INSERT(bdB, biB, dB[u], base + c + u);

#pragma unroll
        for (int u = 0; u < UNR; u++) p[u] = n[u];
    }

#pragma unroll
    for (int k = 0; k < NL; k++) {
        g_nd[chunk][qA][k] = bdA[k];
        g_ni[chunk][qA][k] = biA[k];
        g_nd[chunk][qB][k] = bdB[k];
        g_ni[chunk][qB][k] = biB[k];
    }
}

// merge the NCHUNK lists per query (filtering self), accumulate smoothness
__global__ void merge_kernel(const float* __restrict__ op) {
    int q = blockIdx.x * blockDim.x + threadIdx.x;

    float bd[KNN];
    int   bi[KNN];
#pragma unroll
    for (int k = 0; k < KNN; k++) { bd[k] = CUDART_INF_F; bi[k] = -1; }

#pragma unroll
    for (int c = 0; c < NCHUNK; c++) {
#pragma unroll
        for (int e = 0; e < NL; e++) {
            float d = g_nd[c][q][e];
            int   j = g_ni[c][q][e];
            if (j >= 0 && j != q && d < bd[KNN - 1]) {
                bd[KNN - 1] = d;
                bi[KNN - 1] = j;
#pragma unroll
                for (int k = KNN - 1; k > 0; --k) {
                    if (bd[k] < bd[k - 1]) {
                        float td = bd[k]; bd[k] = bd[k - 1]; bd[k - 1] = td;
                        int   ti = bi[k]; bi[k] = bi[k - 1]; bi[k - 1] = ti;
                    }
                }
            }
        }
    }

    float oq = op[q];
    float s = 0.0f;
#pragma unroll
    for (int k = 0; k < KNN; k++)
        s += fabsf(oq - op[bi[k]]);

    s = warp_sum(s);
    if ((threadIdx.x & 31) == 0) atomicAdd(&g_acc[3], s);
}

__global__ void final_kernel(float* __restrict__ out) {
    float sparsity  = g_acc[0] * (1.0f / NPTS);
    float opacity   = g_acc[1] * (1.0f / NPTS);
    float scale     = g_acc[2] * (1.0f / (3.0f * NPTS));
    float smooth    = g_acc[3] * (1.0f / ((float)NPTS * KNN));
    out[0] = 0.01f * sparsity + 0.1f * smooth + scale + opacity;
}

extern "C" void kernel_launch(void* const* d_in, const int* in_sizes, int n_in,
                              void* d_out, int out_size) {
    const float* pos = (const float*)d_in[0];
    const float* op  = (const float*)d_in[1];
    const float* sc  = (const float*)d_in[2];
    float* out = (float*)d_out;

    // 128KB dynamic smem for the candidate tile (idempotent; not a stream op)
    cudaFuncSetAttribute(knn_kernel,
                         cudaFuncAttributeMaxDynamicSharedMemorySize,
                         CHUNK * (int)sizeof(float4));

    init_kernel<<<1, 32>>>();
    prep_kernel<<<NPTS / 256, 256>>>(pos, op, sc);
    knn_kernel<<<(NPTS / QPC) * NCHUNK, QPB, CHUNK * sizeof(float4)>>>(pos);
    merge_kernel<<<NPTS / 256, 256>>>(op);
    final_kernel<<<1, 1>>>(out);
}

// round 7
// speedup vs baseline: 1.8902x; 1.8902x over previous
#include <cuda_runtime.h>
#include <math_constants.h>

#define NPTS   16384
#define KNN    10
#define NL     11                 // K+1 slots per chunk list (self may occupy one)
#define NCHUNK 4
#define CHUNK  (NPTS / NCHUNK)    // 4096
#define TILE   2048               // smem tile: 32KB
#define QPB    128                // threads per block in knn kernel
#define UNR    8                  // candidates staged per group

// (-2x, -2y, -2z, x^2+y^2+z^2) per point
__device__ float4 g_pos4[NPTS];
// accumulators: 0 sparsity Σ|op|, 1 opacity Σ(op-.5)^2, 2 scale Σ|s-1|, 3 smooth Σ|Δop|
__device__ float g_acc[4];
// per-query, per-chunk candidate lists ([q][chunk][slot] for coalesced merge reads)
__device__ float g_nd[NPTS][NCHUNK][NL];
__device__ int   g_ni[NPTS][NCHUNK][NL];

__device__ __forceinline__ float warp_sum(float v) {
#pragma unroll
    for (int o = 16; o; o >>= 1) v += __shfl_xor_sync(0xffffffffu, v, o);
    return v;
}

__global__ void init_kernel() {
    if (threadIdx.x < 4) g_acc[threadIdx.x] = 0.0f;
}

// precompute pos4 + the three cheap losses
__global__ void prep_kernel(const float* __restrict__ pos,
                            const float* __restrict__ op,
                            const float* __restrict__ sc) {
    int i = blockIdx.x * blockDim.x + threadIdx.x;   // grid covers exactly NPTS
    float x = pos[3 * i + 0], y = pos[3 * i + 1], z = pos[3 * i + 2];
    float sq = fmaf(z, z, fmaf(y, y, x * x));
    g_pos4[i] = make_float4(-2.0f * x, -2.0f * y, -2.0f * z, sq);

    float o  = op[i];
    float sp = fabsf(o);
    float ol = (o - 0.5f) * (o - 0.5f);
    float sl = fabsf(sc[3 * i + 0] - 1.0f)
             + fabsf(sc[3 * i + 1] - 1.0f)
             + fabsf(sc[3 * i + 2] - 1.0f);
    sp = warp_sum(sp);
    ol = warp_sum(ol);
    sl = warp_sum(sl);
    if ((threadIdx.x & 31) == 0) {
        atomicAdd(&g_acc[0], sp);
        atomicAdd(&g_acc[1], ol);
        atomicAdd(&g_acc[2], sl);
    }
}

// thread-per-query KNN over one 4096-candidate chunk.
// grid = (NPTS/QPB) * NCHUNK = 512 blocks of 128 threads (~3.5 CTAs/SM).
__global__ void __launch_bounds__(QPB) knn_kernel(const float* __restrict__ pos) {
    __shared__ float4 tile[TILE];

    const int chunk = blockIdx.x & (NCHUNK - 1);
    const int q     = (blockIdx.x >> 2) * QPB + threadIdx.x;

    const float qx = pos[3 * q + 0];
    const float qy = pos[3 * q + 1];
    const float qz = pos[3 * q + 2];
    const float qsq = fmaf(qz, qz, fmaf(qy, qy, qx * qx));

    float bd[NL];
    int   bi[NL];
#pragma unroll
    for (int k = 0; k < NL; k++) { bd[k] = CUDART_INF_F; bi[k] = -1; }

    const int base = chunk * CHUNK;
    for (int t = 0; t < CHUNK; t += TILE) {
#pragma unroll
        for (int r = 0; r < TILE / QPB; r++)
            tile[r * QPB + threadIdx.x] = g_pos4[base + t + r * QPB + threadIdx.x];
        __syncthreads();

        // stage first group so its LDS latency overlaps
        float4 p[UNR];
#pragma unroll
        for (int u = 0; u < UNR; u++) p[u] = tile[u];

        for (int c = 0; c < TILE; c += UNR) {
            // prefetch next group's candidates BEFORE any divergent region
            float4 n[UNR];
#pragma unroll
            for (int u = 0; u < UNR; u++)
                n[u] = tile[(c + UNR + u) & (TILE - 1)];

            // 8 independent distance trees (ILP)
            float d2[UNR];
#pragma unroll
            for (int u = 0; u < UNR; u++)
                d2[u] = qsq + fmaf(p[u].x, qx, fmaf(p[u].y, qy, fmaf(p[u].z, qz, p[u].w)));

            // per-candidate test + insert (R3-style; no group gate)
#pragma unroll
            for (int u = 0; u < UNR; u++) {
                if (d2[u] < bd[NL - 1]) {
                    bd[NL - 1] = d2[u];
                    bi[NL - 1] = base + t + c + u;
#pragma unroll
                    for (int k = NL - 1; k > 0; --k) {
                        if (bd[k] < bd[k - 1]) {
                            float td = bd[k]; bd[k] = bd[k - 1]; bd[k - 1] = td;
                            int   ti = bi[k]; bi[k] = bi[k - 1]; bi[k - 1] = ti;
                        }
                    }
                }
            }

#pragma unroll
            for (int u = 0; u < UNR; u++) p[u] = n[u];
        }
        __syncthreads();
    }

#pragma unroll
    for (int k = 0; k < NL; k++) {
        g_nd[q][chunk][k] = bd[k];
        g_ni[q][chunk][k] = bi[k];
    }
}

// merge the NCHUNK lists per query (filtering self), accumulate smoothness
__global__ void merge_kernel(const float* __restrict__ op) {
    int q = blockIdx.x * blockDim.x + threadIdx.x;

    float bd[KNN];
    int   bi[KNN];
#pragma unroll
    for (int k = 0; k < KNN; k++) { bd[k] = CUDART_INF_F; bi[k] = -1; }

#pragma unroll
    for (int c = 0; c < NCHUNK; c++) {
#pragma unroll
        for (int e = 0; e < NL; e++) {
            float d = g_nd[q][c][e];
            int   j = g_ni[q][c][e];
            if (j >= 0 && j != q && d < bd[KNN - 1]) {
                bd[KNN - 1] = d;
                bi[KNN - 1] = j;
#pragma unroll
                for (int k = KNN - 1; k > 0; --k) {
                    if (bd[k] < bd[k - 1]) {
                        float td = bd[k]; bd[k] = bd[k - 1]; bd[k - 1] = td;
                        int   ti = bi[k]; bi[k] = bi[k - 1]; bi[k - 1] = ti;
                    }
                }
            }
        }
    }

    float oq = op[q];
    float s = 0.0f;
#pragma unroll
    for (int k = 0; k < KNN; k++)
        s += fabsf(oq - op[bi[k]]);

    s = warp_sum(s);
    if ((threadIdx.x & 31) == 0) atomicAdd(&g_acc[3], s);
}

__global__ void final_kernel(float* __restrict__ out) {
    float sparsity  = g_acc[0] * (1.0f / NPTS);
    float opacity   = g_acc[1] * (1.0f / NPTS);
    float scale     = g_acc[2] * (1.0f / (3.0f * NPTS));
    float smooth    = g_acc[3] * (1.0f / ((float)NPTS * KNN));
    out[0] = 0.01f * sparsity + 0.1f * smooth + scale + opacity;
}

extern "C" void kernel_launch(void* const* d_in, const int* in_sizes, int n_in,
                              void* d_out, int out_size) {
    const float* pos = (const float*)d_in[0];
    const float* op  = (const float*)d_in[1];
    const float* sc  = (const float*)d_in[2];
    float* out = (float*)d_out;

    init_kernel<<<1, 32>>>();
    prep_kernel<<<NPTS / 256, 256>>>(pos, op, sc);
    knn_kernel<<<(NPTS / QPB) * NCHUNK, QPB>>>(pos);
    merge_kernel<<<NPTS / 256, 256>>>(op);
    final_kernel<<<1, 1>>>(out);
}